// round 11
// baseline (speedup 1.0000x reference)
#include <cuda_runtime.h>

#define NROWS 65536
#define FDIM  64
#define EDIM  16
#define NH1   8
#define NH2   4
#define BN_EPS 1e-5f
#define NCTA  128
#define NTHR  128
#define ROWS_CTA 512              /* rows per CTA */
#define ROWS_A (NROWS / NCTA)     /* 512 rows per CTA in phase A */
#define TP 20                     /* padded floats per row per quarter (16 used) */
#define BUF_FLOATS (ROWS_CTA * TP)            /* 10240 floats per array per buffer */
#define BUF_STRIDE (2 * BUF_FLOATS)           /* Xa + Xc per buffer */
#define DYN_BYTES (2 * BUF_STRIDE * 4)        /* 163840 bytes */

typedef unsigned long long u64;

// ---- device scratch ----
__device__ float g_part[NCTA * FDIM];
__device__ float g_hstat[2 * NH1];
__device__ unsigned g_cnt0 = 0, g_cnt1 = 0;
__device__ unsigned g_gen0 = 0, g_gen1 = 0;

// ---- f32x2 helpers ----
__device__ __forceinline__ u64 pk2(float x, float y) {
    u64 r; asm("mov.b64 %0, {%1,%2};" : "=l"(r) : "f"(x), "f"(y)); return r;
}
__device__ __forceinline__ u64 fma2(u64 a, u64 b, u64 c) {
    u64 d; asm("fma.rn.f32x2 %0, %1, %2, %3;" : "=l"(d) : "l"(a), "l"(b), "l"(c)); return d;
}
__device__ __forceinline__ u64 mul2(u64 a, u64 b) {
    u64 d; asm("mul.rn.f32x2 %0, %1, %2;" : "=l"(d) : "l"(a), "l"(b)); return d;
}
__device__ __forceinline__ float2 upk(u64 v) {
    float2 r; asm("mov.b64 {%0,%1}, %2;" : "=f"(r.x), "=f"(r.y) : "l"(v)); return r;
}

// ---- grid barrier (all NCTA CTAs resident; NCTA <= 148, 1 CTA/SM) ----
__device__ __forceinline__ void grid_bar(unsigned* cnt, unsigned* gen) {
    __syncthreads();
    if (threadIdx.x == 0) {
        volatile unsigned* vg = (volatile unsigned*)gen;
        unsigned my = *vg;
        __threadfence();
        if (atomicAdd(cnt, 1) == NCTA - 1) {
            *cnt = 0;
            __threadfence();
            *vg = my + 1;
        } else {
            while (*vg == my) __nanosleep(64);
        }
    }
    __syncthreads();
    __threadfence();
}

__device__ __forceinline__ float ftanh(float x) {
    float xx = fminf(fmaxf(x, -15.f), 15.f);
    float t = __expf(2.f * xx);
    return __fdividef(t - 1.f, t + 1.f);
}

__device__ __forceinline__ void cp16(float* dst, const float4* src) {
    unsigned d = (unsigned)__cvta_generic_to_shared(dst);
    asm volatile("cp.async.cg.shared.global [%0], [%1], 16;" :: "r"(d), "l"(src));
}

extern __shared__ float dynsm[];

// issue cp.async for quarter q into buffer (q&1)
__device__ __forceinline__ void issue_quarter(const float4* Xa4, const float4* Xc4,
                                              int cta, int q, int tid)
{
    size_t gbase = (size_t)cta * ROWS_CTA;
    float* dA = dynsm + (q & 1) * BUF_STRIDE;
    float* dC = dA + BUF_FLOATS;
    #pragma unroll
    for (int it = 0; it < 16; it++) {
        int idx = tid + it * NTHR;
        int row = idx >> 2, c = idx & 3;
        size_t sidx = (gbase + row) * 16 + q * 4 + c;
        int doff = row * TP + c * 4;
        cp16(dA + doff, Xa4 + sidx);
        cp16(dC + doff, Xc4 + sidx);
    }
    asm volatile("cp.async.commit_group;");
}

__global__ void __launch_bounds__(NTHR) k_all(
    const float* __restrict__ Xa, const float* __restrict__ Xc,
    const float* __restrict__ w1, const float* __restrict__ b1,
    const float* __restrict__ w2, const float* __restrict__ b2,
    const float* __restrict__ W1, const float* __restrict__ B1,
    const float* __restrict__ W2, const float* __restrict__ B2,
    const float* __restrict__ L1w, const float* __restrict__ L1b,
    const float* __restrict__ gam, const float* __restrict__ bet,
    const float* __restrict__ L2w, const float* __restrict__ L2b,
    float* __restrict__ out)
{
    __shared__ ulonglong2 sS[FDIM * 12];   // per f: U[4 ull2], B1[4], B2[4]
    __shared__ float      sMhF[FDIM * 24]; // per f: P[8],Q[8],R[8]
    __shared__ u64        sCq[FDIM * 6];   // per f: (m0,m1)(m2,2m3)(2m4,2m5)(w1,b1)(k,0) pre-scaled
    __shared__ float4     spA[NTHR];
    __shared__ float      sRed[2 * FDIM];
    __shared__ float      sXc[FDIM];
    __shared__ float      sStat[16];
    __shared__ float      sFin[32];

    int tid = threadIdx.x;
    int cta = blockIdx.x;
    const float4* Xa4 = (const float4*)Xa;
    const float4* Xc4 = (const float4*)Xc;

    // ---- prologue: quarters 0 and 1 in flight (hidden behind phases A/B) ----
    issue_quarter(Xa4, Xc4, cta, 0, tid);
    issue_quarter(Xa4, Xc4, cta, 1, tid);

    // ================= Phase A: Xc column partial sums =================
    {
        int f4 = tid & 15, rg = tid >> 4;          // 16 quads x 8 row-groups
        float4 acc = make_float4(0.f, 0.f, 0.f, 0.f);
        size_t r = (size_t)cta * ROWS_A + rg;
        #pragma unroll 8
        for (int it = 0; it < ROWS_A / 8; it++, r += 8) {
            float4 v = Xc4[r * 16 + f4];
            acc.x += v.x; acc.y += v.y; acc.z += v.z; acc.w += v.w;
        }
        spA[tid] = acc;
        __syncthreads();
        if (tid < 16) {
            float4 t = make_float4(0.f, 0.f, 0.f, 0.f);
            #pragma unroll
            for (int g = 0; g < 8; g++) {
                float4 v = spA[g * 16 + tid];
                t.x += v.x; t.y += v.y; t.z += v.z; t.w += v.w;
            }
            ((float4*)g_part)[cta * 16 + tid] = t;
        }
        if (cta == 0 && tid < 16) g_hstat[tid] = 0.f;
    }
    grid_bar(&g_cnt0, &g_gen0);

    // ================= Phase B: constants (each CTA redundantly) =================
    {
        int col = tid & 63, grp = tid >> 6;        // 2 groups of 64
        float acc = 0.f;
        #pragma unroll 8
        for (int p = grp; p < NCTA; p += 2)
            acc += __ldcg(&g_part[p * FDIM + col]);
        sRed[grp * FDIM + col] = acc;
    }
    {
        // fill sS: FDIM*4 = 256 float4 slots, 2 per thread
        float4* sSf = (float4*)sS;
        #pragma unroll
        for (int idx = tid; idx < FDIM * 4; idx += NTHR) {
            int f = idx >> 2, j = idx & 3;
            float4 w1v = ((const float4*)W1)[idx];
            float4 w2v = ((const float4*)W2)[idx];
            sSf[f * 12 + j] = make_float4(w1v.x + w2v.x, w1v.y + w2v.y,
                                          w1v.z + w2v.z, w1v.w + w2v.w);
            sSf[f * 12 + 4 + j] = ((const float4*)B1)[idx];
            sSf[f * 12 + 8 + j] = ((const float4*)B2)[idx];
        }
    }
    if (tid < 16) sStat[tid] = 0.f;
    __syncthreads();
    if (tid < FDIM) sXc[tid] = sRed[tid] + sRed[FDIM + tid];
    __syncthreads();
    if (tid < FDIM) {
        int f = tid;
        const float* Uf  = (const float*)&sS[f * 12];
        const float* B1f = Uf + 16;
        const float* B2f = Uf + 32;
        float m0 = 0, m1 = 0, m2 = 0, m3 = 0, m4 = 0, m5 = 0;
        #pragma unroll
        for (int e = 0; e < EDIM; e++) {
            float u = Uf[e], x = B1f[e], y = B2f[e];
            m0 += u * u; m1 += x * x; m2 += y * y;
            m3 += u * x; m4 += u * y; m5 += x * y;
        }
        float xcm = sXc[f] * (1.0f / NROWS);
        float kf = w2[f] * xcm + b2[f];
        const float sF = 1.0f / FDIM;
        const float sQ = 1.0f / 32.0f;
        sCq[f * 6 + 0] = pk2(m0 * sQ, m1 * sQ);
        sCq[f * 6 + 1] = pk2(m2 * sQ, 2.f * m3 * sQ);
        sCq[f * 6 + 2] = pk2(2.f * m4 * sQ, 2.f * m5 * sQ);
        sCq[f * 6 + 3] = pk2(w1[f] * sF, b1[f] * sF);
        sCq[f * 6 + 4] = pk2(kf * sF, 0.f);
        sCq[f * 6 + 5] = 0ull;
    }
    #pragma unroll
    for (int idx = tid; idx < FDIM * NH1; idx += NTHR) {
        int f = idx >> 3, j = idx & 7;
        const float* lr  = L1w + j * (FDIM * EDIM) + f * EDIM;
        const float* Uf  = (const float*)&sS[f * 12];
        const float* B1f = Uf + 16;
        const float* B2f = Uf + 32;
        float P = 0, Q = 0, R = 0;
        #pragma unroll
        for (int e = 0; e < EDIM; e++) {
            float l = lr[e];
            P += Uf[e] * l; Q += B1f[e] * l; R += B2f[e] * l;
        }
        sMhF[f * 24 + j]      = P;
        sMhF[f * 24 + 8 + j]  = Q;
        sMhF[f * 24 + 16 + j] = R;
    }
    __syncthreads();

    // ================= Phase C: 4-quarter pipelined pass, 4 rows/thread =================
    u64 sE[4][8], hv[4][4], ffv[4], qv[4];
    #pragma unroll
    for (int r = 0; r < 4; r++) {
        #pragma unroll
        for (int g = 0; g < 8; g++) sE[r][g] = 0ull;
        #pragma unroll
        for (int j = 0; j < 4; j++) hv[r][j] = 0ull;
        ffv[r] = 0ull; qv[r] = 0ull;
    }

    #pragma unroll 1
    for (int k = 0; k < 4; k++) {
        if (k < 3) asm volatile("cp.async.wait_group 1;" ::: "memory");
        else       asm volatile("cp.async.wait_group 0;" ::: "memory");
        __syncthreads();

        const float* buf = dynsm + (k & 1) * BUF_STRIDE;
        int fbase = k * 16;

        #pragma unroll
        for (int l = 0; l < 4; l++) {
            float av[4][4], cv[4][4];
            #pragma unroll
            for (int r = 0; r < 4; r++) {
                const float* bA = buf + (tid + r * NTHR) * TP;
                float4 a4 = *(const float4*)(bA + l * 4);
                float4 c4 = *(const float4*)(bA + BUF_FLOATS + l * 4);
                av[r][0] = a4.x; av[r][1] = a4.y; av[r][2] = a4.z; av[r][3] = a4.w;
                cv[r][0] = c4.x; cv[r][1] = c4.y; cv[r][2] = c4.z; cv[r][3] = c4.w;
            }
            #pragma unroll
            for (int u = 0; u < 4; u++) {
                int f = fbase + l * 4 + u;
                const ulonglong2* sp = &sS[f * 12];
                const ulonglong2* cq = (const ulonglong2*)&sCq[f * 6];
                const ulonglong2* mh = (const ulonglong2*)&sMhF[f * 24];

                // pair operands for all 4 rows (shared across the three matvecs)
                u64 aa[4], cc[4], acac[4];
                float acs[4];
                #pragma unroll
                for (int r = 0; r < 4; r++) {
                    float a = av[r][u], c = cv[r][u];
                    float ac = a * c;
                    acs[r] = ac;
                    aa[r] = pk2(a, a);
                    cc[r] = pk2(c, c);
                    acac[r] = pk2(ac, ac);
                }

                // ---- ff + quad per row (constants read once per f) ----
                {
                    ulonglong2 cq0 = cq[0];        // (m0,m1) (m2,2m3)
                    ulonglong2 cq1 = cq[1];        // (2m4,2m5) (w1,b1)
                    u64 kq = sCq[f * 6 + 4];       // (k,0)
                    #pragma unroll
                    for (int r = 0; r < 4; r++) {
                        float a = av[r][u], c = cv[r][u], ac = acs[r];
                        u64 P1 = pk2(ac, c);
                        u64 t0 = mul2(P1, P1);
                        u64 t1 = mul2(pk2(a, ac), pk2(a, c));
                        u64 t2 = mul2(acac[r], pk2(a, 1.0f));
                        qv[r] = fma2(t0, cq0.x, qv[r]);
                        qv[r] = fma2(t1, cq0.y, qv[r]);
                        qv[r] = fma2(t2, cq1.x, qv[r]);
                        ffv[r] = fma2(P1, cq1.y, ffv[r]);
                        ffv[r] = fma2(aa[r], kq, ffv[r]);   // lane1 adds a*0
                    }
                }

                // ---- s[e] matvec: constants read inline, serve all 4 rows ----
                #pragma unroll
                for (int g = 0; g < 4; g++) {
                    ulonglong2 uu  = sp[g];
                    ulonglong2 bb1 = sp[4 + g];
                    ulonglong2 bb2 = sp[8 + g];
                    #pragma unroll
                    for (int r = 0; r < 4; r++) {
                        sE[r][2*g]   = fma2(uu.x,  acac[r], sE[r][2*g]);
                        sE[r][2*g+1] = fma2(uu.y,  acac[r], sE[r][2*g+1]);
                        sE[r][2*g]   = fma2(bb1.x, cc[r],   sE[r][2*g]);
                        sE[r][2*g+1] = fma2(bb1.y, cc[r],   sE[r][2*g+1]);
                        sE[r][2*g]   = fma2(bb2.x, aa[r],   sE[r][2*g]);
                        sE[r][2*g+1] = fma2(bb2.y, aa[r],   sE[r][2*g+1]);
                    }
                }
                // ---- h matvec: 6 transient ull2, serve all 4 rows ----
                {
                    ulonglong2 P0 = mh[0], Pq = mh[1];
                    #pragma unroll
                    for (int r = 0; r < 4; r++) {
                        hv[r][0] = fma2(P0.x, acac[r], hv[r][0]);
                        hv[r][1] = fma2(P0.y, acac[r], hv[r][1]);
                        hv[r][2] = fma2(Pq.x, acac[r], hv[r][2]);
                        hv[r][3] = fma2(Pq.y, acac[r], hv[r][3]);
                    }
                }
                {
                    ulonglong2 Q0 = mh[2], Qq = mh[3];
                    #pragma unroll
                    for (int r = 0; r < 4; r++) {
                        hv[r][0] = fma2(Q0.x, cc[r], hv[r][0]);
                        hv[r][1] = fma2(Q0.y, cc[r], hv[r][1]);
                        hv[r][2] = fma2(Qq.x, cc[r], hv[r][2]);
                        hv[r][3] = fma2(Qq.y, cc[r], hv[r][3]);
                    }
                }
                {
                    ulonglong2 R0 = mh[4], Rq = mh[5];
                    #pragma unroll
                    for (int r = 0; r < 4; r++) {
                        hv[r][0] = fma2(R0.x, aa[r], hv[r][0]);
                        hv[r][1] = fma2(R0.y, aa[r], hv[r][1]);
                        hv[r][2] = fma2(Rq.x, aa[r], hv[r][2]);
                        hv[r][3] = fma2(Rq.y, aa[r], hv[r][3]);
                    }
                }
            }
        }
        __syncthreads();              // buffer (k&1) fully consumed
        if (k < 2) issue_quarter(Xa4, Xc4, cta, k + 2, tid);
    }

    // ---- finalize fm parts ----
    float outv[4];
    #pragma unroll
    for (int r = 0; r < 4; r++) {
        u64 ssv = 0ull;
        #pragma unroll
        for (int e = 0; e < 8; e++) ssv = fma2(sE[r][e], sE[r][e], ssv);
        float2 sv = upk(ssv);
        float2 fp = upk(ffv[r]);
        float2 qq = upk(qv[r]);
        outv[r] = (fp.x + fp.y) + (sv.x + sv.y) * (1.0f / 32.0f) - (qq.x + qq.y);
    }

    // ---- h with lin1_b ----
    float lb[8];
    {
        float4 lb0 = __ldg((const float4*)L1b);
        float4 lb1 = __ldg((const float4*)L1b + 1);
        lb[0]=lb0.x; lb[1]=lb0.y; lb[2]=lb0.z; lb[3]=lb0.w;
        lb[4]=lb1.x; lb[5]=lb1.y; lb[6]=lb1.z; lb[7]=lb1.w;
    }
    float hvf[4][8];
    #pragma unroll
    for (int r = 0; r < 4; r++) {
        #pragma unroll
        for (int j = 0; j < 4; j++) {
            float2 t = upk(hv[r][j]);
            hvf[r][2*j]   = t.x + lb[2*j];
            hvf[r][2*j+1] = t.y + lb[2*j+1];
        }
    }

    // ---- BN stats over 4 rows ----
    {
        float st[16];
        #pragma unroll
        for (int j = 0; j < NH1; j++) {
            float s = 0.f, sq = 0.f;
            #pragma unroll
            for (int r = 0; r < 4; r++) { s += hvf[r][j]; sq += hvf[r][j] * hvf[r][j]; }
            st[j] = s; st[8 + j] = sq;
        }
        #pragma unroll
        for (int off = 16; off; off >>= 1) {
            #pragma unroll
            for (int j = 0; j < 16; j++)
                st[j] += __shfl_xor_sync(0xffffffffu, st[j], off);
        }
        if ((tid & 31) == 0) {
            #pragma unroll
            for (int j = 0; j < 16; j++) atomicAdd(&sStat[j], st[j]);
        }
        __syncthreads();
        if (tid < 16) atomicAdd(&g_hstat[tid], sStat[tid]);
    }
    grid_bar(&g_cnt1, &g_gen1);

    // ================= Phase D: BN finalize + tanh + lin2 + store =================
    if (tid < NH1) {
        float sh = __ldcg(&g_hstat[tid]);
        float sq = __ldcg(&g_hstat[NH1 + tid]);
        float mu  = sh * (1.0f / NROWS);
        float var = sq * (1.0f / NROWS) - mu * mu;
        float rs  = rsqrtf(var + BN_EPS);
        float al  = gam[tid] * rs;
        sFin[tid] = al;
        sFin[8 + tid] = bet[tid] - mu * al;
        float v = 0.f;
        #pragma unroll
        for (int j = 0; j < NH2; j++) v += L2w[j * NH1 + tid];
        sFin[16 + tid] = v * (1.0f / NH2);
    }
    if (tid == 0) {
        float cb = 0.f;
        #pragma unroll
        for (int j = 0; j < NH2; j++) cb += L2b[j];
        sFin[24] = cb * (1.0f / NH2);
    }
    __syncthreads();

    #pragma unroll
    for (int r = 0; r < 4; r++) {
        float acc = sFin[24];
        #pragma unroll
        for (int j = 0; j < NH1; j++)
            acc += sFin[16 + j] * ftanh(sFin[j] * hvf[r][j] + sFin[8 + j]);
        out[cta * ROWS_CTA + r * NTHR + tid] = outv[r] + acc;
    }
}

extern "C" void kernel_launch(void* const* d_in, const int* in_sizes, int n_in,
                              void* d_out, int out_size)
{
    const float* Xa  = (const float*)d_in[0];
    const float* Xc  = (const float*)d_in[1];
    const float* w1  = (const float*)d_in[2];
    const float* b1  = (const float*)d_in[3];
    const float* w2  = (const float*)d_in[4];
    const float* b2  = (const float*)d_in[5];
    const float* W1  = (const float*)d_in[6];
    const float* B1  = (const float*)d_in[7];
    const float* W2  = (const float*)d_in[8];
    const float* B2  = (const float*)d_in[9];
    const float* L1w = (const float*)d_in[10];
    const float* L1b = (const float*)d_in[11];
    const float* g1  = (const float*)d_in[12];
    const float* be1 = (const float*)d_in[13];
    const float* L2w = (const float*)d_in[14];
    const float* L2b = (const float*)d_in[15];
    float* out = (float*)d_out;

    cudaFuncSetAttribute(k_all, cudaFuncAttributeMaxDynamicSharedMemorySize, DYN_BYTES);
    k_all<<<NCTA, NTHR, DYN_BYTES>>>(Xa, Xc, w1, b1, w2, b2, W1, B1, W2, B2,
                                     L1w, L1b, g1, be1, L2w, L2b, out);
}

// round 13
// speedup vs baseline: 1.1491x; 1.1491x over previous
#include <cuda_runtime.h>

#define NROWS 65536
#define FDIM  64
#define EDIM  16
#define NH1   8
#define NH2   4
#define BN_EPS 1e-5f
#define NCTA  128
#define NTHR  128
#define ROWS_CTA 512              /* rows per CTA */
#define ROWS_A (NROWS / NCTA)     /* 512 rows per CTA in phase A */
#define TP 20                     /* padded floats per row per quarter (16 used) */
#define BUF_FLOATS (ROWS_CTA * TP)            /* 10240 floats per array per buffer */
#define BUF_STRIDE (2 * BUF_FLOATS)           /* Xa + Xc per buffer */
#define DYN_BYTES (2 * BUF_STRIDE * 4)        /* 163840 bytes */

typedef unsigned long long u64;

// ---- device scratch ----
__device__ float g_part[NCTA * FDIM];
__device__ float g_hstat[2 * NH1];
__device__ unsigned g_cnt0 = 0, g_cnt1 = 0;
__device__ unsigned g_gen0 = 0, g_gen1 = 0;

// ---- f32x2 helpers ----
__device__ __forceinline__ u64 pk2(float x, float y) {
    u64 r; asm("mov.b64 %0, {%1,%2};" : "=l"(r) : "f"(x), "f"(y)); return r;
}
__device__ __forceinline__ u64 fma2(u64 a, u64 b, u64 c) {
    u64 d; asm("fma.rn.f32x2 %0, %1, %2, %3;" : "=l"(d) : "l"(a), "l"(b), "l"(c)); return d;
}
__device__ __forceinline__ u64 mul2(u64 a, u64 b) {
    u64 d; asm("mul.rn.f32x2 %0, %1, %2;" : "=l"(d) : "l"(a), "l"(b)); return d;
}
__device__ __forceinline__ float2 upk(u64 v) {
    float2 r; asm("mov.b64 {%0,%1}, %2;" : "=f"(r.x), "=f"(r.y) : "l"(v)); return r;
}

// ---- grid barrier (all NCTA CTAs resident; NCTA <= 148, 1 CTA/SM) ----
__device__ __forceinline__ void grid_bar(unsigned* cnt, unsigned* gen) {
    __syncthreads();
    if (threadIdx.x == 0) {
        volatile unsigned* vg = (volatile unsigned*)gen;
        unsigned my = *vg;
        __threadfence();
        if (atomicAdd(cnt, 1) == NCTA - 1) {
            *cnt = 0;
            __threadfence();
            *vg = my + 1;
        } else {
            while (*vg == my) __nanosleep(64);
        }
    }
    __syncthreads();
    __threadfence();
}

__device__ __forceinline__ float ftanh(float x) {
    float xx = fminf(fmaxf(x, -15.f), 15.f);
    float t = __expf(2.f * xx);
    return __fdividef(t - 1.f, t + 1.f);
}

extern __shared__ float dynsm[];

// issue cp.async for quarter q into buffer (q&1) — incremental addressing
__device__ __forceinline__ void issue_quarter(const float* Xa, const float* Xc,
                                              int cta, int q, int tid)
{
    int row = tid >> 2, c = tid & 3;
    const float4* A = (const float4*)Xa + (size_t)cta * (ROWS_CTA * 16) + q * 4
                      + row * 16 + c;
    const float4* C = (const float4*)Xc + (size_t)cta * (ROWS_CTA * 16) + q * 4
                      + row * 16 + c;
    unsigned dA = (unsigned)__cvta_generic_to_shared(
                      dynsm + (q & 1) * BUF_STRIDE + row * TP + c * 4);
    unsigned dC = dA + BUF_FLOATS * 4;
    #pragma unroll 4
    for (int it = 0; it < 16; it++) {
        asm volatile("cp.async.cg.shared.global [%0], [%1], 16;" :: "r"(dA), "l"(A));
        asm volatile("cp.async.cg.shared.global [%0], [%1], 16;" :: "r"(dC), "l"(C));
        A += 32 * 16; C += 32 * 16;              // advance 32 rows
        dA += 32 * TP * 4; dC += 32 * TP * 4;
    }
    asm volatile("cp.async.commit_group;");
}

__global__ void __launch_bounds__(NTHR) k_all(
    const float* __restrict__ Xa, const float* __restrict__ Xc,
    const float* __restrict__ w1, const float* __restrict__ b1,
    const float* __restrict__ w2, const float* __restrict__ b2,
    const float* __restrict__ W1, const float* __restrict__ B1,
    const float* __restrict__ W2, const float* __restrict__ B2,
    const float* __restrict__ L1w, const float* __restrict__ L1b,
    const float* __restrict__ gam, const float* __restrict__ bet,
    const float* __restrict__ L2w, const float* __restrict__ L2b,
    float* __restrict__ out)
{
    __shared__ ulonglong2 sS[FDIM * 12];   // per f: U[4 ull2], B1[4], B2[4]
    __shared__ float      sMhF[FDIM * 24]; // per f: P[8],Q[8],R[8]
    __shared__ u64        sCq[FDIM * 6];   // per f: (m0,m1)(m2,2m3)(2m4,2m5)(w1,b1)(k,0) pre-scaled
    __shared__ float4     spA[NTHR];
    __shared__ float      sRed[2 * FDIM];
    __shared__ float      sXc[FDIM];
    __shared__ float      sStat[16];
    __shared__ float      sFin[32];

    int tid = threadIdx.x;
    int cta = blockIdx.x;
    const float4* Xc4 = (const float4*)Xc;

    // ---- prologue: quarters 0 and 1 in flight (hidden behind phases A/B) ----
    issue_quarter(Xa, Xc, cta, 0, tid);
    issue_quarter(Xa, Xc, cta, 1, tid);

    // ================= Phase A: Xc column partial sums =================
    {
        int f4 = tid & 15, rg = tid >> 4;          // 16 quads x 8 row-groups
        float4 acc = make_float4(0.f, 0.f, 0.f, 0.f);
        size_t r = (size_t)cta * ROWS_A + rg;
        #pragma unroll 8
        for (int it = 0; it < ROWS_A / 8; it++, r += 8) {
            float4 v = Xc4[r * 16 + f4];
            acc.x += v.x; acc.y += v.y; acc.z += v.z; acc.w += v.w;
        }
        spA[tid] = acc;
        __syncthreads();
        if (tid < 16) {
            float4 t = make_float4(0.f, 0.f, 0.f, 0.f);
            #pragma unroll
            for (int g = 0; g < 8; g++) {
                float4 v = spA[g * 16 + tid];
                t.x += v.x; t.y += v.y; t.z += v.z; t.w += v.w;
            }
            ((float4*)g_part)[cta * 16 + tid] = t;
        }
        if (cta == 0 && tid < 16) g_hstat[tid] = 0.f;
    }
    grid_bar(&g_cnt0, &g_gen0);

    // ================= Phase B: constants (each CTA redundantly) =================
    {
        int col = tid & 63, grp = tid >> 6;        // 2 groups of 64
        float acc = 0.f;
        #pragma unroll 8
        for (int p = grp; p < NCTA; p += 2)
            acc += __ldcg(&g_part[p * FDIM + col]);
        sRed[grp * FDIM + col] = acc;
    }
    {
        // fill sS: FDIM*4 = 256 float4 slots, 2 per thread
        float4* sSf = (float4*)sS;
        #pragma unroll
        for (int idx = tid; idx < FDIM * 4; idx += NTHR) {
            int f = idx >> 2, j = idx & 3;
            float4 w1v = ((const float4*)W1)[idx];
            float4 w2v = ((const float4*)W2)[idx];
            sSf[f * 12 + j] = make_float4(w1v.x + w2v.x, w1v.y + w2v.y,
                                          w1v.z + w2v.z, w1v.w + w2v.w);
            sSf[f * 12 + 4 + j] = ((const float4*)B1)[idx];
            sSf[f * 12 + 8 + j] = ((const float4*)B2)[idx];
        }
    }
    if (tid < 16) sStat[tid] = 0.f;
    __syncthreads();
    if (tid < FDIM) sXc[tid] = sRed[tid] + sRed[FDIM + tid];
    __syncthreads();
    if (tid < FDIM) {
        int f = tid;
        const float* Uf  = (const float*)&sS[f * 12];
        const float* B1f = Uf + 16;
        const float* B2f = Uf + 32;
        float m0 = 0, m1 = 0, m2 = 0, m3 = 0, m4 = 0, m5 = 0;
        #pragma unroll
        for (int e = 0; e < EDIM; e++) {
            float u = Uf[e], x = B1f[e], y = B2f[e];
            m0 += u * u; m1 += x * x; m2 += y * y;
            m3 += u * x; m4 += u * y; m5 += x * y;
        }
        float xcm = sXc[f] * (1.0f / NROWS);
        float kf = w2[f] * xcm + b2[f];
        const float sF = 1.0f / FDIM;
        const float sQ = 1.0f / 32.0f;
        sCq[f * 6 + 0] = pk2(m0 * sQ, m1 * sQ);
        sCq[f * 6 + 1] = pk2(m2 * sQ, 2.f * m3 * sQ);
        sCq[f * 6 + 2] = pk2(2.f * m4 * sQ, 2.f * m5 * sQ);
        sCq[f * 6 + 3] = pk2(w1[f] * sF, b1[f] * sF);
        sCq[f * 6 + 4] = pk2(kf * sF, 0.f);
        sCq[f * 6 + 5] = 0ull;
    }
    #pragma unroll
    for (int idx = tid; idx < FDIM * NH1; idx += NTHR) {
        int f = idx >> 3, j = idx & 7;
        const float* lr  = L1w + j * (FDIM * EDIM) + f * EDIM;
        const float* Uf  = (const float*)&sS[f * 12];
        const float* B1f = Uf + 16;
        const float* B2f = Uf + 32;
        float P = 0, Q = 0, R = 0;
        #pragma unroll
        for (int e = 0; e < EDIM; e++) {
            float l = lr[e];
            P += Uf[e] * l; Q += B1f[e] * l; R += B2f[e] * l;
        }
        sMhF[f * 24 + j]      = P;
        sMhF[f * 24 + 8 + j]  = Q;
        sMhF[f * 24 + 16 + j] = R;
    }
    __syncthreads();

    // ================= Phase C: 4-quarter pipelined pass, 4 rows/thread =================
    u64 sE[4][8], hv[4][4], ffv[4], qv[4];
    #pragma unroll
    for (int r = 0; r < 4; r++) {
        #pragma unroll
        for (int g = 0; g < 8; g++) sE[r][g] = 0ull;
        #pragma unroll
        for (int j = 0; j < 4; j++) hv[r][j] = 0ull;
        ffv[r] = 0ull; qv[r] = 0ull;
    }

    #pragma unroll 1
    for (int k = 0; k < 4; k++) {
        if (k < 3) asm volatile("cp.async.wait_group 1;" ::: "memory");
        else       asm volatile("cp.async.wait_group 0;" ::: "memory");
        __syncthreads();

        const float* bufA = dynsm + (k & 1) * BUF_STRIDE + tid * TP;

        #pragma unroll 2
        for (int l = 0; l < 4; l++) {
            float4 xa[4], xc[4];
            #pragma unroll
            for (int r = 0; r < 4; r++) {
                xa[r] = *(const float4*)(bufA + r * (NTHR * TP) + l * 4);
                xc[r] = *(const float4*)(bufA + r * (NTHR * TP) + l * 4 + BUF_FLOATS);
            }
            #pragma unroll
            for (int u = 0; u < 4; u++) {
                int f = k * 16 + l * 4 + u;
                const ulonglong2* sp = &sS[f * 12];

                // per-row packed (ac,ac) — only array kept live across sections
                u64 acac[4];
                #pragma unroll
                for (int r = 0; r < 4; r++) {
                    float a = ((const float*)&xa[r])[u];
                    float c = ((const float*)&xc[r])[u];
                    acac[r] = pk2(a * c, a * c);
                }

                // ---- ff + quad per row (constants read once per f) ----
                {
                    const ulonglong2* cqp = (const ulonglong2*)&sCq[f * 6];
                    ulonglong2 cq0 = cqp[0];       // (m0,m1) (m2,2m3)
                    ulonglong2 cq1 = cqp[1];       // (2m4,2m5) (w1,b1)
                    u64 kq = sCq[f * 6 + 4];       // (k,0)
                    #pragma unroll
                    for (int r = 0; r < 4; r++) {
                        float a = ((const float*)&xa[r])[u];
                        float c = ((const float*)&xc[r])[u];
                        float ac = a * c;
                        u64 P1 = pk2(ac, c);
                        qv[r] = fma2(mul2(P1, P1), cq0.x, qv[r]);
                        qv[r] = fma2(mul2(pk2(a, ac), pk2(a, c)), cq0.y, qv[r]);
                        qv[r] = fma2(mul2(acac[r], pk2(a, 1.0f)), cq1.x, qv[r]);
                        ffv[r] = fma2(P1, cq1.y, ffv[r]);
                        ffv[r] = fma2(pk2(a, a), kq, ffv[r]);
                    }
                }

                // ---- s[e] matvec: 12 LDS.128 serve all 4 rows ----
                #pragma unroll
                for (int g = 0; g < 4; g++) {
                    ulonglong2 uu  = sp[g];
                    ulonglong2 bb1 = sp[4 + g];
                    ulonglong2 bb2 = sp[8 + g];
                    #pragma unroll
                    for (int r = 0; r < 4; r++) {
                        float a = ((const float*)&xa[r])[u];
                        float c = ((const float*)&xc[r])[u];
                        u64 cc = pk2(c, c);
                        u64 aa = pk2(a, a);
                        sE[r][2*g]   = fma2(uu.x,  acac[r], sE[r][2*g]);
                        sE[r][2*g+1] = fma2(uu.y,  acac[r], sE[r][2*g+1]);
                        sE[r][2*g]   = fma2(bb1.x, cc,      sE[r][2*g]);
                        sE[r][2*g+1] = fma2(bb1.y, cc,      sE[r][2*g+1]);
                        sE[r][2*g]   = fma2(bb2.x, aa,      sE[r][2*g]);
                        sE[r][2*g+1] = fma2(bb2.y, aa,      sE[r][2*g+1]);
                    }
                }
                // ---- h matvec: 6 transient ull2, serve all 4 rows ----
                {
                    const ulonglong2* mh = (const ulonglong2*)&sMhF[f * 24];
                    {
                        ulonglong2 P0 = mh[0], Pq = mh[1];
                        #pragma unroll
                        for (int r = 0; r < 4; r++) {
                            hv[r][0] = fma2(P0.x, acac[r], hv[r][0]);
                            hv[r][1] = fma2(P0.y, acac[r], hv[r][1]);
                            hv[r][2] = fma2(Pq.x, acac[r], hv[r][2]);
                            hv[r][3] = fma2(Pq.y, acac[r], hv[r][3]);
                        }
                    }
                    {
                        ulonglong2 Q0 = mh[2], Qq = mh[3];
                        #pragma unroll
                        for (int r = 0; r < 4; r++) {
                            float c = ((const float*)&xc[r])[u];
                            u64 cc = pk2(c, c);
                            hv[r][0] = fma2(Q0.x, cc, hv[r][0]);
                            hv[r][1] = fma2(Q0.y, cc, hv[r][1]);
                            hv[r][2] = fma2(Qq.x, cc, hv[r][2]);
                            hv[r][3] = fma2(Qq.y, cc, hv[r][3]);
                        }
                    }
                    {
                        ulonglong2 R0 = mh[4], Rq = mh[5];
                        #pragma unroll
                        for (int r = 0; r < 4; r++) {
                            float a = ((const float*)&xa[r])[u];
                            u64 aa = pk2(a, a);
                            hv[r][0] = fma2(R0.x, aa, hv[r][0]);
                            hv[r][1] = fma2(R0.y, aa, hv[r][1]);
                            hv[r][2] = fma2(Rq.x, aa, hv[r][2]);
                            hv[r][3] = fma2(Rq.y, aa, hv[r][3]);
                        }
                    }
                }
            }
        }
        __syncthreads();              // buffer (k&1) fully consumed
        if (k < 2) issue_quarter(Xa, Xc, cta, k + 2, tid);
    }

    // ---- finalize fm parts ----
    float outv[4];
    #pragma unroll
    for (int r = 0; r < 4; r++) {
        u64 ssv = 0ull;
        #pragma unroll
        for (int e = 0; e < 8; e++) ssv = fma2(sE[r][e], sE[r][e], ssv);
        float2 sv = upk(ssv);
        float2 fp = upk(ffv[r]);
        float2 qq = upk(qv[r]);
        outv[r] = (fp.x + fp.y) + (sv.x + sv.y) * (1.0f / 32.0f) - (qq.x + qq.y);
    }

    // ---- h with lin1_b ----
    float lb[8];
    {
        float4 lb0 = __ldg((const float4*)L1b);
        float4 lb1 = __ldg((const float4*)L1b + 1);
        lb[0]=lb0.x; lb[1]=lb0.y; lb[2]=lb0.z; lb[3]=lb0.w;
        lb[4]=lb1.x; lb[5]=lb1.y; lb[6]=lb1.z; lb[7]=lb1.w;
    }
    float hvf[4][8];
    #pragma unroll
    for (int r = 0; r < 4; r++) {
        #pragma unroll
        for (int j = 0; j < 4; j++) {
            float2 t = upk(hv[r][j]);
            hvf[r][2*j]   = t.x + lb[2*j];
            hvf[r][2*j+1] = t.y + lb[2*j+1];
        }
    }

    // ---- BN stats over 4 rows ----
    {
        float st[16];
        #pragma unroll
        for (int j = 0; j < NH1; j++) {
            float s = 0.f, sq = 0.f;
            #pragma unroll
            for (int r = 0; r < 4; r++) { s += hvf[r][j]; sq += hvf[r][j] * hvf[r][j]; }
            st[j] = s; st[8 + j] = sq;
        }
        #pragma unroll
        for (int off = 16; off; off >>= 1) {
            #pragma unroll
            for (int j = 0; j < 16; j++)
                st[j] += __shfl_xor_sync(0xffffffffu, st[j], off);
        }
        if ((tid & 31) == 0) {
            #pragma unroll
            for (int j = 0; j < 16; j++) atomicAdd(&sStat[j], st[j]);
        }
        __syncthreads();
        if (tid < 16) atomicAdd(&g_hstat[tid], sStat[tid]);
    }
    grid_bar(&g_cnt1, &g_gen1);

    // ================= Phase D: BN finalize + tanh + lin2 + store =================
    if (tid < NH1) {
        float sh = __ldcg(&g_hstat[tid]);
        float sq = __ldcg(&g_hstat[NH1 + tid]);
        float mu  = sh * (1.0f / NROWS);
        float var = sq * (1.0f / NROWS) - mu * mu;
        float rs  = rsqrtf(var + BN_EPS);
        float al  = gam[tid] * rs;
        sFin[tid] = al;
        sFin[8 + tid] = bet[tid] - mu * al;
        float v = 0.f;
        #pragma unroll
        for (int j = 0; j < NH2; j++) v += L2w[j * NH1 + tid];
        sFin[16 + tid] = v * (1.0f / NH2);
    }
    if (tid == 0) {
        float cb = 0.f;
        #pragma unroll
        for (int j = 0; j < NH2; j++) cb += L2b[j];
        sFin[24] = cb * (1.0f / NH2);
    }
    __syncthreads();

    #pragma unroll
    for (int r = 0; r < 4; r++) {
        float acc = sFin[24];
        #pragma unroll
        for (int j = 0; j < NH1; j++)
            acc += sFin[16 + j] * ftanh(sFin[j] * hvf[r][j] + sFin[8 + j]);
        out[cta * ROWS_CTA + r * NTHR + tid] = outv[r] + acc;
    }
}

extern "C" void kernel_launch(void* const* d_in, const int* in_sizes, int n_in,
                              void* d_out, int out_size)
{
    const float* Xa  = (const float*)d_in[0];
    const float* Xc  = (const float*)d_in[1];
    const float* w1  = (const float*)d_in[2];
    const float* b1  = (const float*)d_in[3];
    const float* w2  = (const float*)d_in[4];
    const float* b2  = (const float*)d_in[5];
    const float* W1  = (const float*)d_in[6];
    const float* B1  = (const float*)d_in[7];
    const float* W2  = (const float*)d_in[8];
    const float* B2  = (const float*)d_in[9];
    const float* L1w = (const float*)d_in[10];
    const float* L1b = (const float*)d_in[11];
    const float* g1  = (const float*)d_in[12];
    const float* be1 = (const float*)d_in[13];
    const float* L2w = (const float*)d_in[14];
    const float* L2b = (const float*)d_in[15];
    float* out = (float*)d_out;

    cudaFuncSetAttribute(k_all, cudaFuncAttributeMaxDynamicSharedMemorySize, DYN_BYTES);
    k_all<<<NCTA, NTHR, DYN_BYTES>>>(Xa, Xc, w1, b1, w2, b2, W1, B1, W2, B2,
                                     L1w, L1b, g1, be1, L2w, L2b, out);
}